// round 7
// baseline (speedup 1.0000x reference)
#include <cuda_runtime.h>
#include <mma.h>
#include <cstdint>

using namespace nvcuda;

// Shapes
#define B_  4
#define S_  1024
#define D_  2048
#define H_  16
#define HD_ 128
#define RD_ 64
#define NT  (B_*S_)      // 4096 tokens
#define D3  (3*D_)       // 6144
#define KC  8            // mod-gemm split-K chunks

// ---------------- scratch (static device arrays; allocation-free) -------------
__device__ float g_m3p[KC*B_*D3];
__device__ float g_m3[B_*D3];
__device__ float g_xn[NT*D_];
__device__ float g_qkv[(size_t)NT*D3];
__device__ float g_q[(size_t)B_*H_*S_*HD_];
__device__ float g_k[(size_t)B_*H_*S_*HD_];
__device__ float g_v[(size_t)B_*H_*S_*HD_];
__device__ float g_o[(size_t)NT*D_];
__device__ float g_t[(size_t)NT*D_];
__device__ float g_qkvw[(size_t)D_*D3];      // tf32-rounded qkv_w
__device__ float g_outw[(size_t)D_*D_];      // tf32-rounded out_w

// ---------------- tf32 round-to-nearest helper --------------------------------
__device__ __forceinline__ float rtf32(float x) {
    float r;
    asm("cvt.rna.tf32.f32 %0, %1;" : "=f"(r) : "f"(x));
    return r;
}

// ---------------- cp.async helpers -------------------------------------------
__device__ __forceinline__ void cp_async16(void* smem_dst, const void* gmem_src) {
    uint32_t s = (uint32_t)__cvta_generic_to_shared(smem_dst);
    asm volatile("cp.async.cg.shared.global [%0], [%1], 16;\n" :: "r"(s), "l"(gmem_src));
}
__device__ __forceinline__ void cp_commit() {
    asm volatile("cp.async.commit_group;\n" ::: "memory");
}
__device__ __forceinline__ void cp_wait1() {
    asm volatile("cp.async.wait_group 1;\n" ::: "memory");
}

// ---------------- helpers ----------------------------------------------------
template<int NW>
__device__ __forceinline__ float block_sum(float v, float* sh) {
    #pragma unroll
    for (int o = 16; o > 0; o >>= 1) v += __shfl_xor_sync(0xffffffffu, v, o);
    int w = threadIdx.x >> 5;
    if ((threadIdx.x & 31) == 0) sh[w] = v;
    __syncthreads();
    float r = 0.f;
    #pragma unroll
    for (int i = 0; i < NW; i++) r += sh[i];
    __syncthreads();
    return r;
}

// ---------------- K0: tf32-round weights to scratch ---------------------------
__global__ void k_round(const float* __restrict__ in, float* __restrict__ o) {
    int i = blockIdx.x * 256 + threadIdx.x;
    float4 v = reinterpret_cast<const float4*>(in)[i];
    v.x = rtf32(v.x); v.y = rtf32(v.y); v.z = rtf32(v.z); v.w = rtf32(v.w);
    reinterpret_cast<float4*>(o)[i] = v;
}

// ---------------- K1: mod GEMM (split-K partials, deterministic) --------------
__global__ void k_mod_part(const float* __restrict__ mod,
                           const float* __restrict__ mod_w) {
    __shared__ float sm[B_*256];
    int kc = blockIdx.y;
    int k0 = kc * 256;
    for (int i = threadIdx.x; i < B_*256; i += blockDim.x)
        sm[i] = mod[(i >> 8) * D_ + k0 + (i & 255)];
    __syncthreads();
    int j = blockIdx.x * 128 + threadIdx.x;
    float a0=0.f, a1=0.f, a2=0.f, a3=0.f;
    #pragma unroll 4
    for (int k = 0; k < 256; k++) {
        float w = mod_w[(size_t)(k0 + k) * D3 + j];
        a0 = fmaf(sm[k],       w, a0);
        a1 = fmaf(sm[256 + k], w, a1);
        a2 = fmaf(sm[512 + k], w, a2);
        a3 = fmaf(sm[768 + k], w, a3);
    }
    float* p = g_m3p + (size_t)kc * (B_*D3);
    p[0*D3 + j] = a0; p[1*D3 + j] = a1; p[2*D3 + j] = a2; p[3*D3 + j] = a3;
}

__global__ void k_mod_red(const float* __restrict__ mod_b) {
    int i = blockIdx.x * 256 + threadIdx.x;   // 0 .. B_*D3-1
    float s = 0.f;
    #pragma unroll
    for (int c = 0; c < KC; c++) s += g_m3p[c * (B_*D3) + i];
    g_m3[i] = s + mod_b[i % D3];
}

// ---------------- K2: LayerNorm + AdaLN modulation (tf32-rounded out) ---------
__global__ void k_lnmod(const float* __restrict__ x) {
    __shared__ float sh[8];
    int m = blockIdx.x;       // token
    int b = m >> 10;
    int t = threadIdx.x;
    const float* xr = x + (size_t)m * D_;
    float4 v0 = *reinterpret_cast<const float4*>(xr + t*4);
    float4 v1 = *reinterpret_cast<const float4*>(xr + 1024 + t*4);
    float s = v0.x+v0.y+v0.z+v0.w + v1.x+v1.y+v1.z+v1.w;
    s = block_sum<8>(s, sh);
    float mean = s * (1.f / D_);
    float d0=v0.x-mean, d1=v0.y-mean, d2=v0.z-mean, d3=v0.w-mean;
    float d4=v1.x-mean, d5=v1.y-mean, d6=v1.z-mean, d7=v1.w-mean;
    float ss = d0*d0+d1*d1+d2*d2+d3*d3+d4*d4+d5*d5+d6*d6+d7*d7;
    ss = block_sum<8>(ss, sh);
    float rinv = rsqrtf(ss * (1.f / D_) + 1e-6f);
    const float* mb  = g_m3 + b * D3;        // bias
    const float* msc = mb + D_;              // scale
    int e0 = t*4, e1 = 1024 + t*4;
    float4 o0, o1;
    o0.x = rtf32(d0*rinv*(1.f+msc[e0+0]) + mb[e0+0]);
    o0.y = rtf32(d1*rinv*(1.f+msc[e0+1]) + mb[e0+1]);
    o0.z = rtf32(d2*rinv*(1.f+msc[e0+2]) + mb[e0+2]);
    o0.w = rtf32(d3*rinv*(1.f+msc[e0+3]) + mb[e0+3]);
    o1.x = rtf32(d4*rinv*(1.f+msc[e1+0]) + mb[e1+0]);
    o1.y = rtf32(d5*rinv*(1.f+msc[e1+1]) + mb[e1+1]);
    o1.z = rtf32(d6*rinv*(1.f+msc[e1+2]) + mb[e1+2]);
    o1.w = rtf32(d7*rinv*(1.f+msc[e1+3]) + mb[e1+3]);
    float* xo = g_xn + (size_t)m * D_;
    *reinterpret_cast<float4*>(xo + e0) = o0;
    *reinterpret_cast<float4*>(xo + e1) = o1;
}

// ---------------- tf32 WMMA GEMM, 128x128 tile, 4 warps of 64x64 --------------
// C[M,N] = A[M,K] * B[K,N]; BK=32, cp.async double-buffered.
__global__ void __launch_bounds__(128, 2)
k_gemm(const float* __restrict__ A, int lda,
       const float* __restrict__ B, int ldb,
       float*       __restrict__ C, int ldc, int K) {
    constexpr int BM = 128, BN = 128, BK = 32;
    constexpr int AKP = BK + 8;   // 40 floats/row
    constexpr int BNP = BN + 8;   // 136 floats/row
    constexpr int AS_SZ = BM * AKP;
    constexpr int BS_SZ = BK * BNP;
    extern __shared__ __align__(16) float smem[];
    float* As0 = smem;
    float* As1 = smem + AS_SZ;
    float* Bs0 = smem + 2 * AS_SZ;
    float* Bs1 = smem + 2 * AS_SZ + BS_SZ;

    int tid = threadIdx.x;
    int wid = tid >> 5;
    int wm = wid & 1, wn = wid >> 1;          // 2x2 warps of 64x64
    int bm0 = blockIdx.y * BM, bn0 = blockIdx.x * BN;

    auto load_stage = [&](int kt, int buf) {
        float* As = buf ? As1 : As0;
        float* Bs = buf ? Bs1 : Bs0;
        #pragma unroll
        for (int it = 0; it < 8; it++) {      // A tile: 128 x 32
            int idx = tid + it * 128;
            int r = idx >> 3, c = (idx & 7) << 2;
            cp_async16(&As[r * AKP + c],
                       A + (size_t)(bm0 + r) * lda + kt + c);
        }
        #pragma unroll
        for (int it = 0; it < 8; it++) {      // B tile: 32(k) x 128(n)
            int idx = tid + it * 128;
            int r = idx >> 5, c = (idx & 31) << 2;
            cp_async16(&Bs[r * BNP + c],
                       B + (size_t)(kt + r) * ldb + bn0 + c);
        }
    };

    wmma::fragment<wmma::accumulator, 16, 16, 8, float> acc[4][4];
    #pragma unroll
    for (int i = 0; i < 4; i++)
        #pragma unroll
        for (int j = 0; j < 4; j++) wmma::fill_fragment(acc[i][j], 0.0f);

    int T = K / BK;
    load_stage(0, 0);
    cp_commit();

    for (int t = 0; t < T; t++) {
        if (t + 1 < T) load_stage((t + 1) * BK, (t + 1) & 1);
        cp_commit();
        cp_wait1();
        __syncthreads();
        int buf = t & 1;
        float* As = buf ? As1 : As0;
        float* Bs = buf ? Bs1 : Bs0;
        #pragma unroll
        for (int ks = 0; ks < BK; ks += 8) {
            wmma::fragment<wmma::matrix_a, 16, 16, 8, wmma::precision::tf32, wmma::row_major> af[4];
            #pragma unroll
            for (int i = 0; i < 4; i++)
                wmma::load_matrix_sync(af[i], &As[(wm * 64 + i * 16) * AKP + ks], AKP);
            #pragma unroll
            for (int j = 0; j < 4; j++) {
                wmma::fragment<wmma::matrix_b, 16, 16, 8, wmma::precision::tf32, wmma::row_major> bf;
                wmma::load_matrix_sync(bf, &Bs[ks * BNP + wn * 64 + j * 16], BNP);
                #pragma unroll
                for (int i = 0; i < 4; i++)
                    wmma::mma_sync(acc[i][j], af[i], bf, acc[i][j]);
            }
        }
        __syncthreads();
    }
    #pragma unroll
    for (int i = 0; i < 4; i++)
        #pragma unroll
        for (int j = 0; j < 4; j++)
            wmma::store_matrix_sync(C + (size_t)(bm0 + wm * 64 + i * 16) * ldc + bn0 + wn * 64 + j * 16,
                                    acc[i][j], ldc, wmma::mem_row_major);
}

static const int SMEM_NBT = (2*128*40 + 2*32*136) * 4;   // 75776

// ---------------- K4: qkv bias + RMSNorm + RoPE + layout [B,H,S,HD] -----------
__global__ void k_qkvpost(const float* __restrict__ qkv_b,
                          const float* __restrict__ cosb,
                          const float* __restrict__ sinb,
                          const float* __restrict__ nqw,
                          const float* __restrict__ nkw) {
    __shared__ float sh4[4];
    __shared__ float bufq[HD_], bufk[HD_];
    int tok = blockIdx.x, h = blockIdx.y, d = threadIdx.x;
    int b = tok >> 10, s = tok & 1023;
    size_t base = (size_t)tok * D3 + h * HD_;
    float qv = g_qkv[base + d]          + qkv_b[h * HD_ + d];
    float kv = g_qkv[base + D_ + d]     + qkv_b[D_ + h * HD_ + d];
    float vv = g_qkv[base + 2*D_ + d]   + qkv_b[2*D_ + h * HD_ + d];
    float sq = block_sum<4>(qv * qv, sh4);
    float sk = block_sum<4>(kv * kv, sh4);
    float rq = rsqrtf(sq * (1.f / HD_) + 1e-6f);
    float rk = rsqrtf(sk * (1.f / HD_) + 1e-6f);
    float qn = qv * rq * nqw[d];
    float kn = kv * rk * nkw[d];
    bufq[d] = qn; bufk[d] = kn;
    __syncthreads();
    float qo = qn, ko = kn;
    if (d < RD_) {
        int i = d >> 1;
        float c  = cosb[s * (RD_/2) + i];
        float sn = sinb[s * (RD_/2) + i];
        if ((d & 1) == 0) { qo = bufq[d] * c - bufq[d+1] * sn;
                            ko = bufk[d] * c - bufk[d+1] * sn; }
        else              { qo = bufq[d-1] * sn + bufq[d] * c;
                            ko = bufk[d-1] * sn + bufk[d] * c; }
    }
    size_t ob = ((size_t)(b * H_ + h) * S_ + s) * HD_ + d;
    g_q[ob] = rtf32(qo * 0.08838834764831845f);  // 1/sqrt(HD) folded into Q
    g_k[ob] = rtf32(ko);
    g_v[ob] = rtf32(vv);
}

// ---------------- K5: fused flash attention (QK^T + softmax + PV) -------------
// CTA: 64 q-rows of one (b,h); loops 16 key tiles of 64. 128 threads (4 warps).
// smem float offsets:
#define FO_Q   0        // 64 x 132
#define FO_K   8448     // 64 x 132
#define FO_V   16896    // 64 x 132
#define FO_S   25344    // 64 x 68
#define FO_T   29696    // 64 x 132
#define FO_O   38144    // 64 x 128
#define FO_M   46336    // 64
#define FO_L   46400    // 64
#define FO_A   46464    // 64
#define FO_PM  46528    // 128
#define FO_PS  46656    // 128
static const int SMEM_FLASH = 46784 * 4;    // 187136 bytes

__global__ void __launch_bounds__(128)
k_flash(const float* __restrict__ Qg, const float* __restrict__ Kg,
        const float* __restrict__ Vg, float* __restrict__ Og) {
    extern __shared__ __align__(16) float sm[];
    float* Qs = sm + FO_Q;  float* Ks = sm + FO_K;  float* Vs = sm + FO_V;
    float* Ss = sm + FO_S;  float* Ts = sm + FO_T;  float* Os = sm + FO_O;
    float* mrow = sm + FO_M; float* lrow = sm + FO_L; float* arow = sm + FO_A;
    float* pm = sm + FO_PM;  float* ps = sm + FO_PS;

    int tid = threadIdx.x, wid = tid >> 5;
    int bh = blockIdx.x, qt = blockIdx.y;
    const float* Qp = Qg + ((size_t)bh * S_ + qt * 64) * HD_;
    const float* Kb = Kg + (size_t)bh * S_ * HD_;
    const float* Vb = Vg + (size_t)bh * S_ * HD_;

    // init O and stats
    for (int i = tid; i < 64 * 128; i += 128) Os[i] = 0.f;
    if (tid < 64) { mrow[tid] = -1e30f; lrow[tid] = 0.f; }

    // load a 64x128 tile into smem (ld = 132)
    auto ldtile = [&](float* dst, const float* src) {
        #pragma unroll
        for (int i = 0; i < 16; i++) {
            int idx = tid + i * 128;
            int r = idx >> 5, c = (idx & 31) << 2;
            cp_async16(&dst[r * 132 + c], src + (size_t)r * HD_ + c);
        }
    };
    ldtile(Qs, Qp); ldtile(Ks, Kb); cp_commit();   // group: Q + K0
    ldtile(Vs, Vb); cp_commit();                    // group: V0

    int wm = wid & 1, wn = wid >> 1;
    for (int kt = 0; kt < 16; kt++) {
        cp_wait1();           // all except newest group -> K(kt) (+Q) ready
        __syncthreads();

        // ---- S = Q @ K^T (64x64), warps 2x2 of 32x32 ----
        {
            wmma::fragment<wmma::accumulator, 16, 16, 8, float> acc[2][2];
            #pragma unroll
            for (int i = 0; i < 2; i++)
                #pragma unroll
                for (int j = 0; j < 2; j++) wmma::fill_fragment(acc[i][j], 0.f);
            #pragma unroll
            for (int ks = 0; ks < HD_; ks += 8) {
                wmma::fragment<wmma::matrix_a, 16, 16, 8, wmma::precision::tf32, wmma::row_major> a[2];
                #pragma unroll
                for (int i = 0; i < 2; i++)
                    wmma::load_matrix_sync(a[i], &Qs[(wm * 32 + i * 16) * 132 + ks], 132);
                #pragma unroll
                for (int j = 0; j < 2; j++) {
                    wmma::fragment<wmma::matrix_b, 16, 16, 8, wmma::precision::tf32, wmma::col_major> b;
                    wmma::load_matrix_sync(b, &Ks[(wn * 32 + j * 16) * 132 + ks], 132);
                    #pragma unroll
                    for (int i = 0; i < 2; i++)
                        wmma::mma_sync(acc[i][j], a[i], b, acc[i][j]);
                }
            }
            #pragma unroll
            for (int i = 0; i < 2; i++)
                #pragma unroll
                for (int j = 0; j < 2; j++)
                    wmma::store_matrix_sync(&Ss[(wm * 32 + i * 16) * 68 + wn * 32 + j * 16],
                                            acc[i][j], 68, wmma::mem_row_major);
        }
        __syncthreads();

        // prefetch K(kt+1) — Ks consumed above
        if (kt < 15) ldtile(Ks, Kb + (size_t)(kt + 1) * 64 * HD_);
        cp_commit();

        // ---- online softmax on Ss: 2 threads per row ----
        int r = tid >> 1, hf = tid & 1;
        float* srow = &Ss[r * 68 + hf * 32];
        float mx = -1e30f;
        #pragma unroll
        for (int c = 0; c < 32; c++) mx = fmaxf(mx, srow[c]);
        pm[tid] = mx;
        __syncthreads();
        if (tid < 64) {
            float mnew = fmaxf(mrow[tid], fmaxf(pm[tid * 2], pm[tid * 2 + 1]));
            arow[tid] = __expf(mrow[tid] - mnew);
            mrow[tid] = mnew;
        }
        __syncthreads();
        float mnew = mrow[r];
        float sum = 0.f;
        #pragma unroll
        for (int c = 0; c < 32; c++) {
            float e = __expf(srow[c] - mnew);
            srow[c] = rtf32(e);
            sum += e;
        }
        ps[tid] = sum;
        __syncthreads();
        if (tid < 64) lrow[tid] = lrow[tid] * arow[tid] + ps[tid * 2] + ps[tid * 2 + 1];

        cp_wait1();           // all except newest (K(kt+1)) -> V(kt) ready
        __syncthreads();

        // ---- T = P @ V (64x128), warps: 2(q32) x 2(hd64) ----
        {
            wmma::fragment<wmma::accumulator, 16, 16, 8, float> acc[2][4];
            #pragma unroll
            for (int i = 0; i < 2; i++)
                #pragma unroll
                for (int j = 0; j < 4; j++) wmma::fill_fragment(acc[i][j], 0.f);
            #pragma unroll
            for (int ks = 0; ks < 64; ks += 8) {
                wmma::fragment<wmma::matrix_a, 16, 16, 8, wmma::precision::tf32, wmma::row_major> a[2];
                #pragma unroll
                for (int i = 0; i < 2; i++)
                    wmma::load_matrix_sync(a[i], &Ss[(wm * 32 + i * 16) * 68 + ks], 68);
                #pragma unroll
                for (int j = 0; j < 4; j++) {
                    wmma::fragment<wmma::matrix_b, 16, 16, 8, wmma::precision::tf32, wmma::row_major> b;
                    wmma::load_matrix_sync(b, &Vs[ks * 132 + wn * 64 + j * 16], 132);
                    #pragma unroll
                    for (int i = 0; i < 2; i++)
                        wmma::mma_sync(acc[i][j], a[i], b, acc[i][j]);
                }
            }
            #pragma unroll
            for (int i = 0; i < 2; i++)
                #pragma unroll
                for (int j = 0; j < 4; j++)
                    wmma::store_matrix_sync(&Ts[(wm * 32 + i * 16) * 132 + wn * 64 + j * 16],
                                            acc[i][j], 132, wmma::mem_row_major);
        }
        __syncthreads();

        // prefetch V(kt+1) — Vs consumed above
        if (kt < 15) ldtile(Vs, Vb + (size_t)(kt + 1) * 64 * HD_);
        cp_commit();

        // ---- O = O*alpha + T (column-parallel) ----
        {
            int c = tid;
            #pragma unroll 8
            for (int rr = 0; rr < 64; rr++)
                Os[rr * 128 + c] = Os[rr * 128 + c] * arow[rr] + Ts[rr * 132 + c];
        }
        __syncthreads();
    }

    // write out: g_o[b, qt*64+rr, h*128 + c], rounded for out-proj GEMM
    {
        int c = tid;
        int b = bh >> 4, h = bh & 15;
        float* outp = Og + ((size_t)(b * S_ + qt * 64)) * D_ + h * HD_ + c;
        #pragma unroll 8
        for (int rr = 0; rr < 64; rr++)
            outp[(size_t)rr * D_] = rtf32(Os[rr * 128 + c] / lrow[rr]);
    }
}

// ---------------- K9: bias + gate + residual ----------------------------------
__global__ void k_final(const float* __restrict__ x,
                        const float* __restrict__ out_b,
                        float* __restrict__ out) {
    size_t idx = ((size_t)blockIdx.x * blockDim.x + threadIdx.x) * 4;
    int n = (int)(idx & (D_ - 1));
    int m = (int)(idx >> 11);
    int b = m >> 10;
    const float* gate = g_m3 + b * D3 + 2 * D_;
    float4 t  = *reinterpret_cast<float4*>(&g_t[idx]);
    float4 xr = *reinterpret_cast<const float4*>(&x[idx]);
    float4 o;
    o.x = (t.x + out_b[n+0]) * gate[n+0] + xr.x;
    o.y = (t.y + out_b[n+1]) * gate[n+1] + xr.y;
    o.z = (t.z + out_b[n+2]) * gate[n+2] + xr.z;
    o.w = (t.w + out_b[n+3]) * gate[n+3] + xr.w;
    *reinterpret_cast<float4*>(&out[idx]) = o;
}

// ---------------- launch ------------------------------------------------------
extern "C" void kernel_launch(void* const* d_in, const int* in_sizes, int n_in,
                              void* d_out, int out_size) {
    const float* x     = (const float*)d_in[0];
    const float* mod   = (const float*)d_in[1];
    const float* cosb  = (const float*)d_in[2];
    const float* sinb  = (const float*)d_in[3];
    const float* qkv_w = (const float*)d_in[4];
    const float* qkv_b = (const float*)d_in[5];
    const float* mod_w = (const float*)d_in[6];
    const float* mod_b = (const float*)d_in[7];
    const float* out_w = (const float*)d_in[8];
    const float* out_b = (const float*)d_in[9];
    const float* nqw   = (const float*)d_in[10];
    const float* nkw   = (const float*)d_in[11];
    float* out = (float*)d_out;

    float *p_xn, *p_qkv, *p_q, *p_k, *p_v, *p_o, *p_t, *p_qkvw, *p_outw;
    cudaGetSymbolAddress((void**)&p_xn, g_xn);
    cudaGetSymbolAddress((void**)&p_qkv, g_qkv);
    cudaGetSymbolAddress((void**)&p_q, g_q);
    cudaGetSymbolAddress((void**)&p_k, g_k);
    cudaGetSymbolAddress((void**)&p_v, g_v);
    cudaGetSymbolAddress((void**)&p_o, g_o);
    cudaGetSymbolAddress((void**)&p_t, g_t);
    cudaGetSymbolAddress((void**)&p_qkvw, g_qkvw);
    cudaGetSymbolAddress((void**)&p_outw, g_outw);

    cudaFuncSetAttribute(k_gemm,  cudaFuncAttributeMaxDynamicSharedMemorySize, SMEM_NBT);
    cudaFuncSetAttribute(k_flash, cudaFuncAttributeMaxDynamicSharedMemorySize, SMEM_FLASH);

    // 0) tf32-round the big weights into scratch
    k_round<<<(D_*D3)/(4*256), 256>>>(qkv_w, p_qkvw);
    k_round<<<(D_*D_)/(4*256), 256>>>(out_w, p_outw);
    // 1) m3 = mod @ mod_w + mod_b
    k_mod_part<<<dim3(D3/128, KC), 128>>>(mod, mod_w);
    k_mod_red<<<(B_*D3)/256, 256>>>(mod_b);
    // 2) xn = modulate(layernorm(x)) [tf32-rounded]
    k_lnmod<<<NT, 256>>>(x);
    // 3) qkv = xn @ qkv_w  (bias folded into K4)
    k_gemm<<<dim3(D3/128, NT/128), 128, SMEM_NBT>>>(
        p_xn, D_, p_qkvw, D3, p_qkv, D3, D_);
    // 4) bias + rmsnorm + rope -> q,k,v [B,H,S,HD]  [tf32-rounded]
    k_qkvpost<<<dim3(NT, H_), HD_>>>(qkv_b, cosb, sinb, nqw, nkw);
    // 5) fused attention: scores+softmax+PV -> g_o [B,S,H*HD] [tf32-rounded]
    k_flash<<<dim3(B_*H_, S_/64), 128, SMEM_FLASH>>>(p_q, p_k, p_v, p_o);
    // 6) t = O @ out_w
    k_gemm<<<dim3(D_/128, NT/128), 128, SMEM_NBT>>>(
        p_o, D_, p_outw, D_, p_t, D_, D_);
    // 7) out = (t + out_b) * gate + x
    k_final<<<(NT*D_)/(4*256), 256>>>(x, out_b, out);
}

// round 8
// speedup vs baseline: 1.0454x; 1.0454x over previous
#include <cuda_runtime.h>
#include <mma.h>
#include <cstdint>

using namespace nvcuda;

// Shapes
#define B_  4
#define S_  1024
#define D_  2048
#define H_  16
#define HD_ 128
#define RD_ 64
#define NT  (B_*S_)      // 4096 tokens
#define D3  (3*D_)       // 6144
#define KC  8            // mod-gemm split-K chunks

// ---------------- scratch (static device arrays; allocation-free) -------------
__device__ float g_m3p[KC*B_*D3];
__device__ float g_m3[B_*D3];
__device__ float g_xn[NT*D_];
__device__ float g_qkv[(size_t)NT*D3];
__device__ float g_q[(size_t)B_*H_*S_*HD_];
__device__ float g_k[(size_t)B_*H_*S_*HD_];
__device__ float g_v[(size_t)B_*H_*S_*HD_];
__device__ float g_s[(size_t)B_*H_*S_*S_];   // 256 MB scores
__device__ float g_o[(size_t)NT*D_];
__device__ float g_t[(size_t)NT*D_];
__device__ float g_qkvw[(size_t)D_*D3];      // tf32-rounded qkv_w
__device__ float g_outw[(size_t)D_*D_];      // tf32-rounded out_w

// ---------------- tf32 round-to-nearest helper --------------------------------
__device__ __forceinline__ float rtf32(float x) {
    float r;
    asm("cvt.rna.tf32.f32 %0, %1;" : "=f"(r) : "f"(x));
    return r;
}

// ---------------- cp.async helpers -------------------------------------------
__device__ __forceinline__ void cp_async16(void* smem_dst, const void* gmem_src) {
    uint32_t s = (uint32_t)__cvta_generic_to_shared(smem_dst);
    asm volatile("cp.async.cg.shared.global [%0], [%1], 16;\n" :: "r"(s), "l"(gmem_src));
}
__device__ __forceinline__ void cp_commit() {
    asm volatile("cp.async.commit_group;\n" ::: "memory");
}
__device__ __forceinline__ void cp_wait1() {
    asm volatile("cp.async.wait_group 1;\n" ::: "memory");
}

// ---------------- helpers ----------------------------------------------------
template<int NW>
__device__ __forceinline__ float block_sum(float v, float* sh) {
    #pragma unroll
    for (int o = 16; o > 0; o >>= 1) v += __shfl_xor_sync(0xffffffffu, v, o);
    int w = threadIdx.x >> 5;
    if ((threadIdx.x & 31) == 0) sh[w] = v;
    __syncthreads();
    float r = 0.f;
    #pragma unroll
    for (int i = 0; i < NW; i++) r += sh[i];
    __syncthreads();
    return r;
}

// ---------------- K0: tf32-round weights to scratch ---------------------------
__global__ void k_round(const float* __restrict__ in, float* __restrict__ o) {
    int i = blockIdx.x * 256 + threadIdx.x;
    float4 v = reinterpret_cast<const float4*>(in)[i];
    v.x = rtf32(v.x); v.y = rtf32(v.y); v.z = rtf32(v.z); v.w = rtf32(v.w);
    reinterpret_cast<float4*>(o)[i] = v;
}

// ---------------- K1: mod GEMM (split-K partials, deterministic) --------------
__global__ void k_mod_part(const float* __restrict__ mod,
                           const float* __restrict__ mod_w) {
    __shared__ float sm[B_*256];
    int kc = blockIdx.y;
    int k0 = kc * 256;
    for (int i = threadIdx.x; i < B_*256; i += blockDim.x)
        sm[i] = mod[(i >> 8) * D_ + k0 + (i & 255)];
    __syncthreads();
    int j = blockIdx.x * 128 + threadIdx.x;
    float a0=0.f, a1=0.f, a2=0.f, a3=0.f;
    #pragma unroll 4
    for (int k = 0; k < 256; k++) {
        float w = mod_w[(size_t)(k0 + k) * D3 + j];
        a0 = fmaf(sm[k],       w, a0);
        a1 = fmaf(sm[256 + k], w, a1);
        a2 = fmaf(sm[512 + k], w, a2);
        a3 = fmaf(sm[768 + k], w, a3);
    }
    float* p = g_m3p + (size_t)kc * (B_*D3);
    p[0*D3 + j] = a0; p[1*D3 + j] = a1; p[2*D3 + j] = a2; p[3*D3 + j] = a3;
}

__global__ void k_mod_red(const float* __restrict__ mod_b) {
    int i = blockIdx.x * 256 + threadIdx.x;   // 0 .. B_*D3-1
    float s = 0.f;
    #pragma unroll
    for (int c = 0; c < KC; c++) s += g_m3p[c * (B_*D3) + i];
    g_m3[i] = s + mod_b[i % D3];
}

// ---------------- K2: LayerNorm + AdaLN modulation (tf32-rounded out) ---------
__global__ void k_lnmod(const float* __restrict__ x) {
    __shared__ float sh[8];
    int m = blockIdx.x;       // token
    int b = m >> 10;
    int t = threadIdx.x;
    const float* xr = x + (size_t)m * D_;
    float4 v0 = *reinterpret_cast<const float4*>(xr + t*4);
    float4 v1 = *reinterpret_cast<const float4*>(xr + 1024 + t*4);
    float s = v0.x+v0.y+v0.z+v0.w + v1.x+v1.y+v1.z+v1.w;
    s = block_sum<8>(s, sh);
    float mean = s * (1.f / D_);
    float d0=v0.x-mean, d1=v0.y-mean, d2=v0.z-mean, d3=v0.w-mean;
    float d4=v1.x-mean, d5=v1.y-mean, d6=v1.z-mean, d7=v1.w-mean;
    float ss = d0*d0+d1*d1+d2*d2+d3*d3+d4*d4+d5*d5+d6*d6+d7*d7;
    ss = block_sum<8>(ss, sh);
    float rinv = rsqrtf(ss * (1.f / D_) + 1e-6f);
    const float* mb  = g_m3 + b * D3;        // bias
    const float* msc = mb + D_;              // scale
    int e0 = t*4, e1 = 1024 + t*4;
    float4 o0, o1;
    o0.x = rtf32(d0*rinv*(1.f+msc[e0+0]) + mb[e0+0]);
    o0.y = rtf32(d1*rinv*(1.f+msc[e0+1]) + mb[e0+1]);
    o0.z = rtf32(d2*rinv*(1.f+msc[e0+2]) + mb[e0+2]);
    o0.w = rtf32(d3*rinv*(1.f+msc[e0+3]) + mb[e0+3]);
    o1.x = rtf32(d4*rinv*(1.f+msc[e1+0]) + mb[e1+0]);
    o1.y = rtf32(d5*rinv*(1.f+msc[e1+1]) + mb[e1+1]);
    o1.z = rtf32(d6*rinv*(1.f+msc[e1+2]) + mb[e1+2]);
    o1.w = rtf32(d7*rinv*(1.f+msc[e1+3]) + mb[e1+3]);
    float* xo = g_xn + (size_t)m * D_;
    *reinterpret_cast<float4*>(xo + e0) = o0;
    *reinterpret_cast<float4*>(xo + e1) = o1;
}

// ---------------- tf32 WMMA GEMM, 128x128 tile, 4 warps (attention path) ------
// C[M,N] = A[M,K] * (BT ? B[N,K]^T : B[K,N]); BK=32, cp.async double-buffered.
template<bool BT, bool RND>
__global__ void __launch_bounds__(128, 2)
k_gemm(const float* __restrict__ A, int lda, long long sA1, long long sA2,
       const float* __restrict__ B, int ldb, long long sB1, long long sB2,
       float*       __restrict__ C, int ldc, long long sC1, long long sC2,
       int K, int zdiv) {
    constexpr int BM = 128, BN = 128, BK = 32;
    constexpr int AKP = BK + 8;
    constexpr int BNP = BN + 8;
    constexpr int AS_SZ = BM * AKP;
    constexpr int BS_SZ = BT ? (BN * AKP) : (BK * BNP);
    extern __shared__ __align__(16) float smem[];
    float* As0 = smem;
    float* As1 = smem + AS_SZ;
    float* Bs0 = smem + 2 * AS_SZ;
    float* Bs1 = smem + 2 * AS_SZ + BS_SZ;

    int z  = blockIdx.z;
    int z1 = z / zdiv, z2 = z - z1 * zdiv;
    A += (size_t)(z1 * sA1 + z2 * sA2);
    B += (size_t)(z1 * sB1 + z2 * sB2);
    C += (size_t)(z1 * sC1 + z2 * sC2);

    int tid = threadIdx.x;
    int wid = tid >> 5;
    int wm = wid & 1, wn = wid >> 1;          // 2x2 warps of 64x64
    int bm0 = blockIdx.y * BM, bn0 = blockIdx.x * BN;

    auto load_stage = [&](int kt, int buf) {
        float* As = buf ? As1 : As0;
        float* Bs = buf ? Bs1 : Bs0;
        #pragma unroll
        for (int it = 0; it < 8; it++) {      // A tile: 128 x 32
            int idx = tid + it * 128;
            int r = idx >> 3, c = (idx & 7) << 2;
            cp_async16(&As[r * AKP + c],
                       A + (size_t)(bm0 + r) * lda + kt + c);
        }
        #pragma unroll
        for (int it = 0; it < 8; it++) {
            int idx = tid + it * 128;
            if (BT) {
                int r = idx >> 3, c = (idx & 7) << 2;
                cp_async16(&Bs[r * AKP + c],
                           B + (size_t)(bn0 + r) * ldb + kt + c);
            } else {
                int r = idx >> 5, c = (idx & 31) << 2;
                cp_async16(&Bs[r * BNP + c],
                           B + (size_t)(kt + r) * ldb + bn0 + c);
            }
        }
    };

    wmma::fragment<wmma::accumulator, 16, 16, 8, float> acc[4][4];
    #pragma unroll
    for (int i = 0; i < 4; i++)
        #pragma unroll
        for (int j = 0; j < 4; j++) wmma::fill_fragment(acc[i][j], 0.0f);

    int T = K / BK;
    load_stage(0, 0);
    cp_commit();

    for (int t = 0; t < T; t++) {
        if (t + 1 < T) load_stage((t + 1) * BK, (t + 1) & 1);
        cp_commit();
        cp_wait1();
        __syncthreads();
        int buf = t & 1;
        float* As = buf ? As1 : As0;
        float* Bs = buf ? Bs1 : Bs0;
        #pragma unroll
        for (int ks = 0; ks < BK; ks += 8) {
            wmma::fragment<wmma::matrix_a, 16, 16, 8, wmma::precision::tf32, wmma::row_major> af[4];
            #pragma unroll
            for (int i = 0; i < 4; i++)
                wmma::load_matrix_sync(af[i], &As[(wm * 64 + i * 16) * AKP + ks], AKP);
            #pragma unroll
            for (int j = 0; j < 4; j++) {
                if (BT) {
                    wmma::fragment<wmma::matrix_b, 16, 16, 8, wmma::precision::tf32, wmma::col_major> bf;
                    wmma::load_matrix_sync(bf, &Bs[(wn * 64 + j * 16) * AKP + ks], AKP);
                    #pragma unroll
                    for (int i = 0; i < 4; i++)
                        wmma::mma_sync(acc[i][j], af[i], bf, acc[i][j]);
                } else {
                    wmma::fragment<wmma::matrix_b, 16, 16, 8, wmma::precision::tf32, wmma::row_major> bf;
                    wmma::load_matrix_sync(bf, &Bs[ks * BNP + wn * 64 + j * 16], BNP);
                    #pragma unroll
                    for (int i = 0; i < 4; i++)
                        wmma::mma_sync(acc[i][j], af[i], bf, acc[i][j]);
                }
            }
        }
        __syncthreads();
    }
    #pragma unroll
    for (int i = 0; i < 4; i++)
        #pragma unroll
        for (int j = 0; j < 4; j++) {
            if (RND) {
                #pragma unroll
                for (int e = 0; e < acc[i][j].num_elements; e++)
                    acc[i][j].x[e] = rtf32(acc[i][j].x[e]);
            }
            wmma::store_matrix_sync(C + (size_t)(bm0 + wm * 64 + i * 16) * ldc + bn0 + wn * 64 + j * 16,
                                    acc[i][j], ldc, wmma::mem_row_major);
        }
}

static const int SMEM_BT  = (2*128*40 + 2*128*40) * 4;   // 81920
static const int SMEM_NBT = (2*128*40 + 2*32*136) * 4;   // 75776

// ---------------- wide tf32 WMMA GEMM, 128x256 tile, 8 warps of 64x64 ---------
// C[M,N] = A[M,K] * B[K,N]; BK=32, cp.async double-buffered. (projection path)
__global__ void __launch_bounds__(256)
k_gemm2(const float* __restrict__ A, int lda,
        const float* __restrict__ B, int ldb,
        float*       __restrict__ C, int ldc, int K) {
    constexpr int BM = 128, BN = 256, BK = 32;
    constexpr int AKP = BK + 8;    // 40 floats/row
    constexpr int BNP = BN + 8;    // 264 floats/row
    constexpr int AS_SZ = BM * AKP;    // 5120
    constexpr int BS_SZ = BK * BNP;    // 8448
    extern __shared__ __align__(16) float smem[];
    float* As0 = smem;
    float* As1 = smem + AS_SZ;
    float* Bs0 = smem + 2 * AS_SZ;
    float* Bs1 = smem + 2 * AS_SZ + BS_SZ;

    int tid = threadIdx.x;
    int wid = tid >> 5;
    int wm = wid & 1, wn = wid >> 1;          // 2(M) x 4(N) warps of 64x64
    int bm0 = blockIdx.y * BM, bn0 = blockIdx.x * BN;

    auto load_stage = [&](int kt, int buf) {
        float* As = buf ? As1 : As0;
        float* Bs = buf ? Bs1 : Bs0;
        #pragma unroll
        for (int it = 0; it < 4; it++) {      // A tile: 128 x 32
            int idx = tid + it * 256;
            int r = idx >> 3, c = (idx & 7) << 2;
            cp_async16(&As[r * AKP + c],
                       A + (size_t)(bm0 + r) * lda + kt + c);
        }
        #pragma unroll
        for (int it = 0; it < 8; it++) {      // B tile: 32(k) x 256(n)
            int idx = tid + it * 256;
            int r = idx >> 6, c = (idx & 63) << 2;
            cp_async16(&Bs[r * BNP + c],
                       B + (size_t)(kt + r) * ldb + bn0 + c);
        }
    };

    wmma::fragment<wmma::accumulator, 16, 16, 8, float> acc[4][4];
    #pragma unroll
    for (int i = 0; i < 4; i++)
        #pragma unroll
        for (int j = 0; j < 4; j++) wmma::fill_fragment(acc[i][j], 0.0f);

    int T = K / BK;
    load_stage(0, 0);
    cp_commit();

    for (int t = 0; t < T; t++) {
        if (t + 1 < T) load_stage((t + 1) * BK, (t + 1) & 1);
        cp_commit();
        cp_wait1();
        __syncthreads();
        int buf = t & 1;
        float* As = buf ? As1 : As0;
        float* Bs = buf ? Bs1 : Bs0;
        #pragma unroll
        for (int ks = 0; ks < BK; ks += 8) {
            wmma::fragment<wmma::matrix_a, 16, 16, 8, wmma::precision::tf32, wmma::row_major> af[4];
            #pragma unroll
            for (int i = 0; i < 4; i++)
                wmma::load_matrix_sync(af[i], &As[(wm * 64 + i * 16) * AKP + ks], AKP);
            #pragma unroll
            for (int j = 0; j < 4; j++) {
                wmma::fragment<wmma::matrix_b, 16, 16, 8, wmma::precision::tf32, wmma::row_major> bf;
                wmma::load_matrix_sync(bf, &Bs[ks * BNP + wn * 64 + j * 16], BNP);
                #pragma unroll
                for (int i = 0; i < 4; i++)
                    wmma::mma_sync(acc[i][j], af[i], bf, acc[i][j]);
            }
        }
        __syncthreads();
    }
    #pragma unroll
    for (int i = 0; i < 4; i++)
        #pragma unroll
        for (int j = 0; j < 4; j++)
            wmma::store_matrix_sync(C + (size_t)(bm0 + wm * 64 + i * 16) * ldc + bn0 + wn * 64 + j * 16,
                                    acc[i][j], ldc, wmma::mem_row_major);
}

static const int SMEM_G2 = (2*128*40 + 2*32*264) * 4;    // 108544

// ---------------- K4: qkv bias + RMSNorm + RoPE + layout [B,H,S,HD] -----------
__global__ void k_qkvpost(const float* __restrict__ qkv_b,
                          const float* __restrict__ cosb,
                          const float* __restrict__ sinb,
                          const float* __restrict__ nqw,
                          const float* __restrict__ nkw) {
    __shared__ float sh4[4];
    __shared__ float bufq[HD_], bufk[HD_];
    int tok = blockIdx.x, h = blockIdx.y, d = threadIdx.x;
    int b = tok >> 10, s = tok & 1023;
    size_t base = (size_t)tok * D3 + h * HD_;
    float qv = g_qkv[base + d]          + qkv_b[h * HD_ + d];
    float kv = g_qkv[base + D_ + d]     + qkv_b[D_ + h * HD_ + d];
    float vv = g_qkv[base + 2*D_ + d]   + qkv_b[2*D_ + h * HD_ + d];
    float sq = block_sum<4>(qv * qv, sh4);
    float sk = block_sum<4>(kv * kv, sh4);
    float rq = rsqrtf(sq * (1.f / HD_) + 1e-6f);
    float rk = rsqrtf(sk * (1.f / HD_) + 1e-6f);
    float qn = qv * rq * nqw[d];
    float kn = kv * rk * nkw[d];
    bufq[d] = qn; bufk[d] = kn;
    __syncthreads();
    float qo = qn, ko = kn;
    if (d < RD_) {
        int i = d >> 1;
        float c  = cosb[s * (RD_/2) + i];
        float sn = sinb[s * (RD_/2) + i];
        if ((d & 1) == 0) { qo = bufq[d] * c - bufq[d+1] * sn;
                            ko = bufk[d] * c - bufk[d+1] * sn; }
        else              { qo = bufq[d-1] * sn + bufq[d] * c;
                            ko = bufk[d-1] * sn + bufk[d] * c; }
    }
    size_t ob = ((size_t)(b * H_ + h) * S_ + s) * HD_ + d;
    g_q[ob] = rtf32(qo * 0.08838834764831845f);  // 1/sqrt(HD) folded into Q
    g_k[ob] = rtf32(ko);
    g_v[ob] = rtf32(vv);
}

// ---------------- K6: softmax over rows of g_s (warp per row, float4) ---------
__global__ void k_softmax() {
    int r = blockIdx.x * 8 + (threadIdx.x >> 5);
    int lane = threadIdx.x & 31;
    float4* row = reinterpret_cast<float4*>(g_s + (size_t)r * S_);
    float4 x[8];
    float mx = -1e30f;
    #pragma unroll
    for (int i = 0; i < 8; i++) {
        x[i] = row[lane + 32*i];
        mx = fmaxf(mx, fmaxf(fmaxf(x[i].x, x[i].y), fmaxf(x[i].z, x[i].w)));
    }
    #pragma unroll
    for (int o = 16; o > 0; o >>= 1) mx = fmaxf(mx, __shfl_xor_sync(0xffffffffu, mx, o));
    float sm = 0.f;
    #pragma unroll
    for (int i = 0; i < 8; i++) {
        x[i].x = __expf(x[i].x - mx); x[i].y = __expf(x[i].y - mx);
        x[i].z = __expf(x[i].z - mx); x[i].w = __expf(x[i].w - mx);
        sm += x[i].x + x[i].y + x[i].z + x[i].w;
    }
    #pragma unroll
    for (int o = 16; o > 0; o >>= 1) sm += __shfl_xor_sync(0xffffffffu, sm, o);
    float inv = 1.f / sm;
    #pragma unroll
    for (int i = 0; i < 8; i++) {
        x[i].x = rtf32(x[i].x * inv); x[i].y = rtf32(x[i].y * inv);
        x[i].z = rtf32(x[i].z * inv); x[i].w = rtf32(x[i].w * inv);
        row[lane + 32*i] = x[i];
    }
}

// ---------------- K9: bias + gate + residual ----------------------------------
__global__ void k_final(const float* __restrict__ x,
                        const float* __restrict__ out_b,
                        float* __restrict__ out) {
    size_t idx = ((size_t)blockIdx.x * blockDim.x + threadIdx.x) * 4;
    int n = (int)(idx & (D_ - 1));
    int m = (int)(idx >> 11);
    int b = m >> 10;
    const float* gate = g_m3 + b * D3 + 2 * D_;
    float4 t  = *reinterpret_cast<float4*>(&g_t[idx]);
    float4 xr = *reinterpret_cast<const float4*>(&x[idx]);
    float4 o;
    o.x = (t.x + out_b[n+0]) * gate[n+0] + xr.x;
    o.y = (t.y + out_b[n+1]) * gate[n+1] + xr.y;
    o.z = (t.z + out_b[n+2]) * gate[n+2] + xr.z;
    o.w = (t.w + out_b[n+3]) * gate[n+3] + xr.w;
    *reinterpret_cast<float4*>(&out[idx]) = o;
}

// ---------------- launch ------------------------------------------------------
extern "C" void kernel_launch(void* const* d_in, const int* in_sizes, int n_in,
                              void* d_out, int out_size) {
    const float* x     = (const float*)d_in[0];
    const float* mod   = (const float*)d_in[1];
    const float* cosb  = (const float*)d_in[2];
    const float* sinb  = (const float*)d_in[3];
    const float* qkv_w = (const float*)d_in[4];
    const float* qkv_b = (const float*)d_in[5];
    const float* mod_w = (const float*)d_in[6];
    const float* mod_b = (const float*)d_in[7];
    const float* out_w = (const float*)d_in[8];
    const float* out_b = (const float*)d_in[9];
    const float* nqw   = (const float*)d_in[10];
    const float* nkw   = (const float*)d_in[11];
    float* out = (float*)d_out;

    float *p_xn, *p_qkv, *p_q, *p_k, *p_v, *p_s, *p_o, *p_t, *p_qkvw, *p_outw;
    cudaGetSymbolAddress((void**)&p_xn, g_xn);
    cudaGetSymbolAddress((void**)&p_qkv, g_qkv);
    cudaGetSymbolAddress((void**)&p_q, g_q);
    cudaGetSymbolAddress((void**)&p_k, g_k);
    cudaGetSymbolAddress((void**)&p_v, g_v);
    cudaGetSymbolAddress((void**)&p_s, g_s);
    cudaGetSymbolAddress((void**)&p_o, g_o);
    cudaGetSymbolAddress((void**)&p_t, g_t);
    cudaGetSymbolAddress((void**)&p_qkvw, g_qkvw);
    cudaGetSymbolAddress((void**)&p_outw, g_outw);

    cudaFuncSetAttribute(k_gemm<false,true>, cudaFuncAttributeMaxDynamicSharedMemorySize, SMEM_NBT);
    cudaFuncSetAttribute(k_gemm<true,false>, cudaFuncAttributeMaxDynamicSharedMemorySize, SMEM_BT);
    cudaFuncSetAttribute(k_gemm2, cudaFuncAttributeMaxDynamicSharedMemorySize, SMEM_G2);

    // 0) tf32-round the big weights into scratch
    k_round<<<(D_*D3)/(4*256), 256>>>(qkv_w, p_qkvw);
    k_round<<<(D_*D_)/(4*256), 256>>>(out_w, p_outw);
    // 1) m3 = mod @ mod_w + mod_b
    k_mod_part<<<dim3(D3/128, KC), 128>>>(mod, mod_w);
    k_mod_red<<<(B_*D3)/256, 256>>>(mod_b);
    // 2) xn = modulate(layernorm(x)) [tf32-rounded]
    k_lnmod<<<NT, 256>>>(x);
    // 3) qkv = xn @ qkv_w  (wide 128x256 GEMM; bias folded into K4)
    k_gemm2<<<dim3(D3/256, NT/128), 256, SMEM_G2>>>(
        p_xn, D_, p_qkvw, D3, p_qkv, D3, D_);
    // 4) bias + rmsnorm + rope -> q,k,v [B,H,S,HD]  [tf32-rounded]
    k_qkvpost<<<dim3(NT, H_), HD_>>>(qkv_b, cosb, sinb, nqw, nkw);
    // 5) scores = Q @ K^T (per b,h); Q already carries 1/sqrt(HD)
    k_gemm<true,false><<<dim3(S_/128, S_/128, B_*H_), 128, SMEM_BT>>>(
        p_q, HD_, (long long)S_*HD_, 0,
        p_k, HD_, (long long)S_*HD_, 0,
        p_s, S_,  (long long)S_*S_,  0, HD_, 1);
    // 6) softmax rows [tf32-rounded]
    k_softmax<<<(B_*H_*S_)/8, 256>>>();
    // 7) O = P @ V  -> [B,S,H,HD] (strided C) [accum rounded for next GEMM]
    k_gemm<false,true><<<dim3(1, S_/128, B_*H_), 128, SMEM_NBT>>>(
        p_s, S_,  (long long)H_*S_*S_,  (long long)S_*S_,
        p_v, HD_, (long long)H_*S_*HD_, (long long)S_*HD_,
        p_o, D_,  (long long)S_*D_,     (long long)HD_, S_, H_);
    // 8) t = O @ out_w  (wide 128x256 GEMM)
    k_gemm2<<<dim3(D_/256, NT/128), 256, SMEM_G2>>>(
        p_o, D_, p_outw, D_, p_t, D_, D_);
    // 9) out = (t + out_b) * gate + x
    k_final<<<(NT*D_)/(4*256), 256>>>(x, out_b, out);
}

// round 9
// speedup vs baseline: 1.1114x; 1.0631x over previous
#include <cuda_runtime.h>
#include <mma.h>
#include <cstdint>

using namespace nvcuda;

// Shapes
#define B_  4
#define S_  1024
#define D_  2048
#define H_  16
#define HD_ 128
#define RD_ 64
#define NT  (B_*S_)      // 4096 tokens
#define D3  (3*D_)       // 6144
#define KC  8            // mod-gemm split-K chunks

// ---------------- scratch (static device arrays; allocation-free) -------------
__device__ float g_m3p[KC*B_*D3];
__device__ float g_m3[B_*D3];
__device__ float g_xn[NT*D_];
__device__ float g_qkv[(size_t)NT*D3];
__device__ float g_q[(size_t)B_*H_*S_*HD_];
__device__ float g_k[(size_t)B_*H_*S_*HD_];
__device__ float g_v[(size_t)B_*H_*S_*HD_];
__device__ float g_s[(size_t)B_*H_*S_*S_];   // 256 MB scores
__device__ float g_o[(size_t)NT*D_];
__device__ float g_t[(size_t)NT*D_];
__device__ float g_qkvw[(size_t)D_*D3];      // tf32-rounded qkv_w
__device__ float g_outw[(size_t)D_*D_];      // tf32-rounded out_w

// ---------------- tf32 round-to-nearest helper --------------------------------
__device__ __forceinline__ float rtf32(float x) {
    float r;
    asm("cvt.rna.tf32.f32 %0, %1;" : "=f"(r) : "f"(x));
    return r;
}

// ---------------- cp.async helpers -------------------------------------------
__device__ __forceinline__ void cp_async16(void* smem_dst, const void* gmem_src) {
    uint32_t s = (uint32_t)__cvta_generic_to_shared(smem_dst);
    asm volatile("cp.async.cg.shared.global [%0], [%1], 16;\n" :: "r"(s), "l"(gmem_src));
}
__device__ __forceinline__ void cp_commit() {
    asm volatile("cp.async.commit_group;\n" ::: "memory");
}
__device__ __forceinline__ void cp_wait1() {
    asm volatile("cp.async.wait_group 1;\n" ::: "memory");
}

// ---------------- helpers ----------------------------------------------------
template<int NW>
__device__ __forceinline__ float block_sum(float v, float* sh) {
    #pragma unroll
    for (int o = 16; o > 0; o >>= 1) v += __shfl_xor_sync(0xffffffffu, v, o);
    int w = threadIdx.x >> 5;
    if ((threadIdx.x & 31) == 0) sh[w] = v;
    __syncthreads();
    float r = 0.f;
    #pragma unroll
    for (int i = 0; i < NW; i++) r += sh[i];
    __syncthreads();
    return r;
}

// ---------------- K0: tf32-round weights to scratch ---------------------------
__global__ void k_round(const float* __restrict__ in, float* __restrict__ o) {
    int i = blockIdx.x * 256 + threadIdx.x;
    float4 v = reinterpret_cast<const float4*>(in)[i];
    v.x = rtf32(v.x); v.y = rtf32(v.y); v.z = rtf32(v.z); v.w = rtf32(v.w);
    reinterpret_cast<float4*>(o)[i] = v;
}

// ---------------- K1: mod GEMM (split-K partials, deterministic) --------------
__global__ void k_mod_part(const float* __restrict__ mod,
                           const float* __restrict__ mod_w) {
    __shared__ float sm[B_*256];
    int kc = blockIdx.y;
    int k0 = kc * 256;
    for (int i = threadIdx.x; i < B_*256; i += blockDim.x)
        sm[i] = mod[(i >> 8) * D_ + k0 + (i & 255)];
    __syncthreads();
    int j = blockIdx.x * 128 + threadIdx.x;
    float a0=0.f, a1=0.f, a2=0.f, a3=0.f;
    #pragma unroll 4
    for (int k = 0; k < 256; k++) {
        float w = mod_w[(size_t)(k0 + k) * D3 + j];
        a0 = fmaf(sm[k],       w, a0);
        a1 = fmaf(sm[256 + k], w, a1);
        a2 = fmaf(sm[512 + k], w, a2);
        a3 = fmaf(sm[768 + k], w, a3);
    }
    float* p = g_m3p + (size_t)kc * (B_*D3);
    p[0*D3 + j] = a0; p[1*D3 + j] = a1; p[2*D3 + j] = a2; p[3*D3 + j] = a3;
}

__global__ void k_mod_red(const float* __restrict__ mod_b) {
    int i = blockIdx.x * 256 + threadIdx.x;   // 0 .. B_*D3-1
    float s = 0.f;
    #pragma unroll
    for (int c = 0; c < KC; c++) s += g_m3p[c * (B_*D3) + i];
    g_m3[i] = s + mod_b[i % D3];
}

// ---------------- K2: LayerNorm + AdaLN modulation (tf32-rounded out) ---------
__global__ void k_lnmod(const float* __restrict__ x) {
    __shared__ float sh[8];
    int m = blockIdx.x;       // token
    int b = m >> 10;
    int t = threadIdx.x;
    const float* xr = x + (size_t)m * D_;
    float4 v0 = *reinterpret_cast<const float4*>(xr + t*4);
    float4 v1 = *reinterpret_cast<const float4*>(xr + 1024 + t*4);
    float s = v0.x+v0.y+v0.z+v0.w + v1.x+v1.y+v1.z+v1.w;
    s = block_sum<8>(s, sh);
    float mean = s * (1.f / D_);
    float d0=v0.x-mean, d1=v0.y-mean, d2=v0.z-mean, d3=v0.w-mean;
    float d4=v1.x-mean, d5=v1.y-mean, d6=v1.z-mean, d7=v1.w-mean;
    float ss = d0*d0+d1*d1+d2*d2+d3*d3+d4*d4+d5*d5+d6*d6+d7*d7;
    ss = block_sum<8>(ss, sh);
    float rinv = rsqrtf(ss * (1.f / D_) + 1e-6f);
    const float* mb  = g_m3 + b * D3;        // bias
    const float* msc = mb + D_;              // scale
    int e0 = t*4, e1 = 1024 + t*4;
    float4 o0, o1;
    o0.x = rtf32(d0*rinv*(1.f+msc[e0+0]) + mb[e0+0]);
    o0.y = rtf32(d1*rinv*(1.f+msc[e0+1]) + mb[e0+1]);
    o0.z = rtf32(d2*rinv*(1.f+msc[e0+2]) + mb[e0+2]);
    o0.w = rtf32(d3*rinv*(1.f+msc[e0+3]) + mb[e0+3]);
    o1.x = rtf32(d4*rinv*(1.f+msc[e1+0]) + mb[e1+0]);
    o1.y = rtf32(d5*rinv*(1.f+msc[e1+1]) + mb[e1+1]);
    o1.z = rtf32(d6*rinv*(1.f+msc[e1+2]) + mb[e1+2]);
    o1.w = rtf32(d7*rinv*(1.f+msc[e1+3]) + mb[e1+3]);
    float* xo = g_xn + (size_t)m * D_;
    *reinterpret_cast<float4*>(xo + e0) = o0;
    *reinterpret_cast<float4*>(xo + e1) = o1;
}

// ---------------- tf32 WMMA GEMM, 2-stage (BT attention path only) ------------
// C[M,N] = A[M,K] * B[N,K]^T; 128x128 tile, 4 warps of 64x64, BK=32.
__global__ void __launch_bounds__(128, 2)
k_gemmBT(const float* __restrict__ A, int lda, long long sA1,
         const float* __restrict__ B, int ldb, long long sB1,
         float*       __restrict__ C, int ldc, long long sC1,
         int K) {
    constexpr int BM = 128, BN = 128, BK = 32;
    constexpr int AKP = BK + 8;
    constexpr int AS_SZ = BM * AKP;
    constexpr int BS_SZ = BN * AKP;
    extern __shared__ __align__(16) float smem[];
    float* As0 = smem;
    float* As1 = smem + AS_SZ;
    float* Bs0 = smem + 2 * AS_SZ;
    float* Bs1 = smem + 2 * AS_SZ + BS_SZ;

    int z  = blockIdx.z;
    A += (size_t)z * sA1;
    B += (size_t)z * sB1;
    C += (size_t)z * sC1;

    int tid = threadIdx.x;
    int wid = tid >> 5;
    int wm = wid & 1, wn = wid >> 1;
    int bm0 = blockIdx.y * BM, bn0 = blockIdx.x * BN;

    auto load_stage = [&](int kt, int buf) {
        float* As = buf ? As1 : As0;
        float* Bs = buf ? Bs1 : Bs0;
        #pragma unroll
        for (int it = 0; it < 8; it++) {
            int idx = tid + it * 128;
            int r = idx >> 3, c = (idx & 7) << 2;
            cp_async16(&As[r * AKP + c],
                       A + (size_t)(bm0 + r) * lda + kt + c);
        }
        #pragma unroll
        for (int it = 0; it < 8; it++) {
            int idx = tid + it * 128;
            int r = idx >> 3, c = (idx & 7) << 2;
            cp_async16(&Bs[r * AKP + c],
                       B + (size_t)(bn0 + r) * ldb + kt + c);
        }
    };

    wmma::fragment<wmma::accumulator, 16, 16, 8, float> acc[4][4];
    #pragma unroll
    for (int i = 0; i < 4; i++)
        #pragma unroll
        for (int j = 0; j < 4; j++) wmma::fill_fragment(acc[i][j], 0.0f);

    int T = K / BK;
    load_stage(0, 0);
    cp_commit();

    for (int t = 0; t < T; t++) {
        if (t + 1 < T) load_stage((t + 1) * BK, (t + 1) & 1);
        cp_commit();
        cp_wait1();
        __syncthreads();
        int buf = t & 1;
        float* As = buf ? As1 : As0;
        float* Bs = buf ? Bs1 : Bs0;
        #pragma unroll
        for (int ks = 0; ks < BK; ks += 8) {
            wmma::fragment<wmma::matrix_a, 16, 16, 8, wmma::precision::tf32, wmma::row_major> af[4];
            #pragma unroll
            for (int i = 0; i < 4; i++)
                wmma::load_matrix_sync(af[i], &As[(wm * 64 + i * 16) * AKP + ks], AKP);
            #pragma unroll
            for (int j = 0; j < 4; j++) {
                wmma::fragment<wmma::matrix_b, 16, 16, 8, wmma::precision::tf32, wmma::col_major> bf;
                wmma::load_matrix_sync(bf, &Bs[(wn * 64 + j * 16) * AKP + ks], AKP);
                #pragma unroll
                for (int i = 0; i < 4; i++)
                    wmma::mma_sync(acc[i][j], af[i], bf, acc[i][j]);
            }
        }
        __syncthreads();
    }
    #pragma unroll
    for (int i = 0; i < 4; i++)
        #pragma unroll
        for (int j = 0; j < 4; j++)
            wmma::store_matrix_sync(C + (size_t)(bm0 + wm * 64 + i * 16) * ldc + bn0 + wn * 64 + j * 16,
                                    acc[i][j], ldc, wmma::mem_row_major);
}

static const int SMEM_BT = (2*128*40 + 2*128*40) * 4;   // 81920

// ---------------- tf32 WMMA GEMM, 3-stage, ONE sync per tile ------------------
// C[M,N] = A[M,K] * B[K,N]; 128x128 tile, 4 warps of 64x64, BK=32.
// 3 circular buffers; iteration t: wait tile t, sync, issue tile t+2, compute.
template<bool RND>
__global__ void __launch_bounds__(128, 2)
k_gemm3(const float* __restrict__ A, int lda, long long sA1, long long sA2,
        const float* __restrict__ B, int ldb, long long sB1, long long sB2,
        float*       __restrict__ C, int ldc, long long sC1, long long sC2,
        int K, int zdiv) {
    constexpr int BM = 128, BN = 128, BK = 32;
    constexpr int AKP = BK + 8;    // 40
    constexpr int BNP = BN + 8;    // 136
    constexpr int AS_SZ = BM * AKP;    // 5120
    constexpr int BS_SZ = BK * BNP;    // 4352
    constexpr int STG = AS_SZ + BS_SZ; // 9472 floats per stage
    extern __shared__ __align__(16) float smem[];

    int z  = blockIdx.z;
    int z1 = z / zdiv, z2 = z - z1 * zdiv;
    A += (size_t)(z1 * sA1 + z2 * sA2);
    B += (size_t)(z1 * sB1 + z2 * sB2);
    C += (size_t)(z1 * sC1 + z2 * sC2);

    int tid = threadIdx.x;
    int wid = tid >> 5;
    int wm = wid & 1, wn = wid >> 1;          // 2x2 warps of 64x64
    int bm0 = blockIdx.y * BM, bn0 = blockIdx.x * BN;

    auto load_stage = [&](int kt, int s) {
        float* As = smem + s * STG;
        float* Bs = As + AS_SZ;
        #pragma unroll
        for (int it = 0; it < 8; it++) {      // A tile: 128 x 32
            int idx = tid + it * 128;
            int r = idx >> 3, c = (idx & 7) << 2;
            cp_async16(&As[r * AKP + c],
                       A + (size_t)(bm0 + r) * lda + kt + c);
        }
        #pragma unroll
        for (int it = 0; it < 8; it++) {      // B tile: 32(k) x 128(n)
            int idx = tid + it * 128;
            int r = idx >> 5, c = (idx & 31) << 2;
            cp_async16(&Bs[r * BNP + c],
                       B + (size_t)(kt + r) * ldb + bn0 + c);
        }
    };

    wmma::fragment<wmma::accumulator, 16, 16, 8, float> acc[4][4];
    #pragma unroll
    for (int i = 0; i < 4; i++)
        #pragma unroll
        for (int j = 0; j < 4; j++) wmma::fill_fragment(acc[i][j], 0.0f);

    int T = K / BK;
    load_stage(0, 0);  cp_commit();
    load_stage(BK, 1); cp_commit();

    int sbuf = 0;       // stage of tile t (t % 3)
    for (int t = 0; t < T; t++) {
        cp_wait1();                     // tile t landed (for this thread)
        __syncthreads();                // visibility + everyone done with t-1
        int nt = t + 2;
        if (nt < T) {
            int ns = sbuf + 2; if (ns >= 3) ns -= 3;
            load_stage(nt * BK, ns);    // buffer (t+2)%3: last read at t-1
            cp_commit();
        }
        float* As = smem + sbuf * STG;
        float* Bs = As + AS_SZ;
        #pragma unroll
        for (int ks = 0; ks < BK; ks += 8) {
            wmma::fragment<wmma::matrix_a, 16, 16, 8, wmma::precision::tf32, wmma::row_major> af[4];
            #pragma unroll
            for (int i = 0; i < 4; i++)
                wmma::load_matrix_sync(af[i], &As[(wm * 64 + i * 16) * AKP + ks], AKP);
            #pragma unroll
            for (int j = 0; j < 4; j++) {
                wmma::fragment<wmma::matrix_b, 16, 16, 8, wmma::precision::tf32, wmma::row_major> bf;
                wmma::load_matrix_sync(bf, &Bs[ks * BNP + wn * 64 + j * 16], BNP);
                #pragma unroll
                for (int i = 0; i < 4; i++)
                    wmma::mma_sync(acc[i][j], af[i], bf, acc[i][j]);
            }
        }
        if (++sbuf == 3) sbuf = 0;
    }
    #pragma unroll
    for (int i = 0; i < 4; i++)
        #pragma unroll
        for (int j = 0; j < 4; j++) {
            if (RND) {
                #pragma unroll
                for (int e = 0; e < acc[i][j].num_elements; e++)
                    acc[i][j].x[e] = rtf32(acc[i][j].x[e]);
            }
            wmma::store_matrix_sync(C + (size_t)(bm0 + wm * 64 + i * 16) * ldc + bn0 + wn * 64 + j * 16,
                                    acc[i][j], ldc, wmma::mem_row_major);
        }
}

static const int SMEM_G3 = 3 * (128*40 + 32*136) * 4;   // 113664

// ---------------- K4: qkv bias + RMSNorm + RoPE + layout [B,H,S,HD] -----------
__global__ void k_qkvpost(const float* __restrict__ qkv_b,
                          const float* __restrict__ cosb,
                          const float* __restrict__ sinb,
                          const float* __restrict__ nqw,
                          const float* __restrict__ nkw) {
    __shared__ float sh4[4];
    __shared__ float bufq[HD_], bufk[HD_];
    int tok = blockIdx.x, h = blockIdx.y, d = threadIdx.x;
    int b = tok >> 10, s = tok & 1023;
    size_t base = (size_t)tok * D3 + h * HD_;
    float qv = g_qkv[base + d]          + qkv_b[h * HD_ + d];
    float kv = g_qkv[base + D_ + d]     + qkv_b[D_ + h * HD_ + d];
    float vv = g_qkv[base + 2*D_ + d]   + qkv_b[2*D_ + h * HD_ + d];
    float sq = block_sum<4>(qv * qv, sh4);
    float sk = block_sum<4>(kv * kv, sh4);
    float rq = rsqrtf(sq * (1.f / HD_) + 1e-6f);
    float rk = rsqrtf(sk * (1.f / HD_) + 1e-6f);
    float qn = qv * rq * nqw[d];
    float kn = kv * rk * nkw[d];
    bufq[d] = qn; bufk[d] = kn;
    __syncthreads();
    float qo = qn, ko = kn;
    if (d < RD_) {
        int i = d >> 1;
        float c  = cosb[s * (RD_/2) + i];
        float sn = sinb[s * (RD_/2) + i];
        if ((d & 1) == 0) { qo = bufq[d] * c - bufq[d+1] * sn;
                            ko = bufk[d] * c - bufk[d+1] * sn; }
        else              { qo = bufq[d-1] * sn + bufq[d] * c;
                            ko = bufk[d-1] * sn + bufk[d] * c; }
    }
    size_t ob = ((size_t)(b * H_ + h) * S_ + s) * HD_ + d;
    g_q[ob] = rtf32(qo * 0.08838834764831845f);  // 1/sqrt(HD) folded into Q
    g_k[ob] = rtf32(ko);
    g_v[ob] = rtf32(vv);
}

// ---------------- K6: softmax over rows of g_s (warp per row, float4) ---------
__global__ void k_softmax() {
    int r = blockIdx.x * 8 + (threadIdx.x >> 5);
    int lane = threadIdx.x & 31;
    float4* row = reinterpret_cast<float4*>(g_s + (size_t)r * S_);
    float4 x[8];
    float mx = -1e30f;
    #pragma unroll
    for (int i = 0; i < 8; i++) {
        x[i] = row[lane + 32*i];
        mx = fmaxf(mx, fmaxf(fmaxf(x[i].x, x[i].y), fmaxf(x[i].z, x[i].w)));
    }
    #pragma unroll
    for (int o = 16; o > 0; o >>= 1) mx = fmaxf(mx, __shfl_xor_sync(0xffffffffu, mx, o));
    float sm = 0.f;
    #pragma unroll
    for (int i = 0; i < 8; i++) {
        x[i].x = __expf(x[i].x - mx); x[i].y = __expf(x[i].y - mx);
        x[i].z = __expf(x[i].z - mx); x[i].w = __expf(x[i].w - mx);
        sm += x[i].x + x[i].y + x[i].z + x[i].w;
    }
    #pragma unroll
    for (int o = 16; o > 0; o >>= 1) sm += __shfl_xor_sync(0xffffffffu, sm, o);
    float inv = 1.f / sm;
    #pragma unroll
    for (int i = 0; i < 8; i++) {
        x[i].x = rtf32(x[i].x * inv); x[i].y = rtf32(x[i].y * inv);
        x[i].z = rtf32(x[i].z * inv); x[i].w = rtf32(x[i].w * inv);
        row[lane + 32*i] = x[i];
    }
}

// ---------------- K9: bias + gate + residual ----------------------------------
__global__ void k_final(const float* __restrict__ x,
                        const float* __restrict__ out_b,
                        float* __restrict__ out) {
    size_t idx = ((size_t)blockIdx.x * blockDim.x + threadIdx.x) * 4;
    int n = (int)(idx & (D_ - 1));
    int m = (int)(idx >> 11);
    int b = m >> 10;
    const float* gate = g_m3 + b * D3 + 2 * D_;
    float4 t  = *reinterpret_cast<float4*>(&g_t[idx]);
    float4 xr = *reinterpret_cast<const float4*>(&x[idx]);
    float4 o;
    o.x = (t.x + out_b[n+0]) * gate[n+0] + xr.x;
    o.y = (t.y + out_b[n+1]) * gate[n+1] + xr.y;
    o.z = (t.z + out_b[n+2]) * gate[n+2] + xr.z;
    o.w = (t.w + out_b[n+3]) * gate[n+3] + xr.w;
    *reinterpret_cast<float4*>(&out[idx]) = o;
}

// ---------------- launch ------------------------------------------------------
extern "C" void kernel_launch(void* const* d_in, const int* in_sizes, int n_in,
                              void* d_out, int out_size) {
    const float* x     = (const float*)d_in[0];
    const float* mod   = (const float*)d_in[1];
    const float* cosb  = (const float*)d_in[2];
    const float* sinb  = (const float*)d_in[3];
    const float* qkv_w = (const float*)d_in[4];
    const float* qkv_b = (const float*)d_in[5];
    const float* mod_w = (const float*)d_in[6];
    const float* mod_b = (const float*)d_in[7];
    const float* out_w = (const float*)d_in[8];
    const float* out_b = (const float*)d_in[9];
    const float* nqw   = (const float*)d_in[10];
    const float* nkw   = (const float*)d_in[11];
    float* out = (float*)d_out;

    float *p_xn, *p_qkv, *p_q, *p_k, *p_v, *p_s, *p_o, *p_t, *p_qkvw, *p_outw;
    cudaGetSymbolAddress((void**)&p_xn, g_xn);
    cudaGetSymbolAddress((void**)&p_qkv, g_qkv);
    cudaGetSymbolAddress((void**)&p_q, g_q);
    cudaGetSymbolAddress((void**)&p_k, g_k);
    cudaGetSymbolAddress((void**)&p_v, g_v);
    cudaGetSymbolAddress((void**)&p_s, g_s);
    cudaGetSymbolAddress((void**)&p_o, g_o);
    cudaGetSymbolAddress((void**)&p_t, g_t);
    cudaGetSymbolAddress((void**)&p_qkvw, g_qkvw);
    cudaGetSymbolAddress((void**)&p_outw, g_outw);

    cudaFuncSetAttribute(k_gemm3<false>, cudaFuncAttributeMaxDynamicSharedMemorySize, SMEM_G3);
    cudaFuncSetAttribute(k_gemm3<true>,  cudaFuncAttributeMaxDynamicSharedMemorySize, SMEM_G3);
    cudaFuncSetAttribute(k_gemmBT, cudaFuncAttributeMaxDynamicSharedMemorySize, SMEM_BT);

    // 0) tf32-round the big weights into scratch
    k_round<<<(D_*D3)/(4*256), 256>>>(qkv_w, p_qkvw);
    k_round<<<(D_*D_)/(4*256), 256>>>(out_w, p_outw);
    // 1) m3 = mod @ mod_w + mod_b
    k_mod_part<<<dim3(D3/128, KC), 128>>>(mod, mod_w);
    k_mod_red<<<(B_*D3)/256, 256>>>(mod_b);
    // 2) xn = modulate(layernorm(x)) [tf32-rounded]
    k_lnmod<<<NT, 256>>>(x);
    // 3) qkv = xn @ qkv_w  (3-stage GEMM; bias folded into K4)
    k_gemm3<false><<<dim3(D3/128, NT/128), 128, SMEM_G3>>>(
        p_xn, D_, 0, 0, p_qkvw, D3, 0, 0, p_qkv, D3, 0, 0, D_, 1);
    // 4) bias + rmsnorm + rope -> q,k,v [B,H,S,HD]  [tf32-rounded]
    k_qkvpost<<<dim3(NT, H_), HD_>>>(qkv_b, cosb, sinb, nqw, nkw);
    // 5) scores = Q @ K^T (per b,h); Q already carries 1/sqrt(HD)
    k_gemmBT<<<dim3(S_/128, S_/128, B_*H_), 128, SMEM_BT>>>(
        p_q, HD_, (long long)S_*HD_,
        p_k, HD_, (long long)S_*HD_,
        p_s, S_,  (long long)S_*S_, HD_);
    // 6) softmax rows [tf32-rounded]
    k_softmax<<<(B_*H_*S_)/8, 256>>>();
    // 7) O = P @ V  -> [B,S,H,HD] (strided C) [accum rounded for next GEMM]
    k_gemm3<true><<<dim3(1, S_/128, B_*H_), 128, SMEM_G3>>>(
        p_s, S_,  (long long)H_*S_*S_,  (long long)S_*S_,
        p_v, HD_, (long long)H_*S_*HD_, (long long)S_*HD_,
        p_o, D_,  (long long)S_*D_,     (long long)HD_, S_, H_);
    // 8) t = O @ out_w  (3-stage GEMM)
    k_gemm3<false><<<dim3(D_/128, NT/128), 128, SMEM_G3>>>(
        p_o, D_, 0, 0, p_outw, D_, 0, 0, p_t, D_, 0, 0, D_, 1);
    // 9) out = (t + out_b) * gate + x
    k_final<<<(NT*D_)/(4*256), 256>>>(x, out_b, out);
}